// round 9
// baseline (speedup 1.0000x reference)
#include <cuda_runtime.h>
#include <math.h>

// ---------------------------------------------------------------------------
// MultiHeadAttention: B=4, S=2048, D_MODEL=1024, HEADS=16, D_K=D_V=64
// Inputs (metadata order): q, k, v, mask, Wq, Wk, Wv, Wo, ln_gamma, ln_beta
// Output: concat( out[B,S,1024], attn[B,H,S,S] ) as float32
// ---------------------------------------------------------------------------

#define B_   4
#define S_   2048
#define DM   1024
#define H_   16
#define DK   64
#define BS_  (B_ * S_)                 // 8192
#define ATTN_OFF ((size_t)BS_ * DM)    // 8388608
#define NEG_INF_F (-1000000000.0f)

// Scratch (static device globals; no runtime allocation)
__device__ float g_qn [BS_ * DM];
__device__ float g_Qh [BS_ * DM];
__device__ float g_Kh [BS_ * DM];
__device__ float g_Vh [BS_ * DM];
__device__ float g_ctx[BS_ * DM];
__device__ float g_rowmax[B_ * H_ * S_];

// ---------------------------------------------------------------------------
// Block-wide sum over 256 threads (8 warps). Caller supplies 8-float smem.
// ---------------------------------------------------------------------------
__device__ __forceinline__ float blk_sum256(float v, float* sbuf) {
    #pragma unroll
    for (int o = 16; o; o >>= 1) v += __shfl_xor_sync(0xffffffffu, v, o);
    int t = threadIdx.x;
    if ((t & 31) == 0) sbuf[t >> 5] = v;
    __syncthreads();
    float r = sbuf[0] + sbuf[1] + sbuf[2] + sbuf[3] +
              sbuf[4] + sbuf[5] + sbuf[6] + sbuf[7];
    __syncthreads();
    return r;
}

// ---------------------------------------------------------------------------
// LayerNorm over rows of 1024. One block (256 thr) per row, float4 per thread.
// ---------------------------------------------------------------------------
__global__ void __launch_bounds__(256) ln_kernel(
    const float* __restrict__ x, const float* __restrict__ gamma,
    const float* __restrict__ beta, float* __restrict__ y)
{
    __shared__ float sbuf[8];
    int row = blockIdx.x;
    int t = threadIdx.x;
    const float4* xr = (const float4*)(x + (size_t)row * DM);
    float4 v = xr[t];
    float s = v.x + v.y + v.z + v.w;
    float tot = blk_sum256(s, sbuf);
    float mean = tot * (1.0f / DM);
    float dx = v.x - mean, dy = v.y - mean, dz = v.z - mean, dw = v.w - mean;
    float s2 = dx*dx + dy*dy + dz*dz + dw*dw;
    float tot2 = blk_sum256(s2, sbuf);
    float rstd = rsqrtf(tot2 * (1.0f / DM) + 1e-6f);
    float4 g  = ((const float4*)gamma)[t];
    float4 bb = ((const float4*)beta)[t];
    float4 o;
    o.x = dx * rstd * g.x + bb.x;
    o.y = dy * rstd * g.y + bb.y;
    o.z = dz * rstd * g.z + bb.z;
    o.w = dw * rstd * g.w + bb.w;
    ((float4*)(y + (size_t)row * DM))[t] = o;
}

// ---------------------------------------------------------------------------
// SGEMM: C(MxN) = A(MxK) @ B(KxN) [+ R], row-major, M%128==N%128==0, K%8==0.
// 128x128 block tile, BK=8, 256 threads, 8x8 micro-tile (split quadrants).
// ---------------------------------------------------------------------------
__global__ void __launch_bounds__(256) sgemm_kernel(
    const float* __restrict__ A, const float* __restrict__ Bm,
    const float* __restrict__ R, float* __restrict__ C,
    int M, int N, int K)
{
    __shared__ float As[8][132];
    __shared__ float Bs[8][128];
    int tid = threadIdx.x;
    int tx = tid & 15, ty = tid >> 4;
    int bm = blockIdx.y << 7, bn = blockIdx.x << 7;

    float acc[8][8];
    #pragma unroll
    for (int i = 0; i < 8; i++)
        #pragma unroll
        for (int j = 0; j < 8; j++) acc[i][j] = 0.0f;

    int arow = tid >> 1;
    int acol = (tid & 1) << 2;
    int brow = tid >> 5;
    int bcol = (tid & 31) << 2;
    const float* Ap = A + (size_t)(bm + arow) * K + acol;
    const float* Bp = Bm + (size_t)brow * N + bn + bcol;

    for (int k0 = 0; k0 < K; k0 += 8) {
        float4 av = *(const float4*)(Ap + k0);
        float4 bv = *(const float4*)(Bp + (size_t)k0 * N);
        As[acol + 0][arow] = av.x;
        As[acol + 1][arow] = av.y;
        As[acol + 2][arow] = av.z;
        As[acol + 3][arow] = av.w;
        *(float4*)&Bs[brow][bcol] = bv;
        __syncthreads();
        #pragma unroll
        for (int kk = 0; kk < 8; kk++) {
            float a[8], b[8];
            *(float4*)(a)     = *(const float4*)&As[kk][ty << 2];
            *(float4*)(a + 4) = *(const float4*)&As[kk][64 + (ty << 2)];
            *(float4*)(b)     = *(const float4*)&Bs[kk][tx << 2];
            *(float4*)(b + 4) = *(const float4*)&Bs[kk][64 + (tx << 2)];
            #pragma unroll
            for (int i = 0; i < 8; i++)
                #pragma unroll
                for (int j = 0; j < 8; j++) acc[i][j] += a[i] * b[j];
        }
        __syncthreads();
    }

    #pragma unroll
    for (int i = 0; i < 8; i++) {
        int r = bm + ((i < 4) ? ((ty << 2) + i) : (64 + (ty << 2) + i - 4));
        float* crow = C + (size_t)r * N + bn;
        float4 c0 = make_float4(acc[i][0], acc[i][1], acc[i][2], acc[i][3]);
        float4 c1 = make_float4(acc[i][4], acc[i][5], acc[i][6], acc[i][7]);
        if (R) {
            const float* rrow = R + (size_t)r * N + bn;
            float4 r0 = *(const float4*)(rrow + (tx << 2));
            float4 r1 = *(const float4*)(rrow + 64 + (tx << 2));
            c0.x += r0.x; c0.y += r0.y; c0.z += r0.z; c0.w += r0.w;
            c1.x += r1.x; c1.y += r1.y; c1.z += r1.z; c1.w += r1.w;
        }
        *(float4*)(crow + (tx << 2))      = c0;
        *(float4*)(crow + 64 + (tx << 2)) = c1;
    }
}

// ---------------------------------------------------------------------------
// Scores: attn_raw[b,h,q,k] = (Q[b,q,h,:] . K[b,k,h,:]) / 8, masked to -1e9.
// Also records per-row max. 128q x 128k tile per block, inner dim 64.
// Dynamic smem: Qs[64][132] + Ks[64][132] = 67584 B.
// ---------------------------------------------------------------------------
__global__ void __launch_bounds__(256) scores_kernel(
    const float* __restrict__ Qh, const float* __restrict__ Kh,
    const int* __restrict__ mask, float* __restrict__ attn,
    float* __restrict__ rowmax)
{
    extern __shared__ float sm[];
    float* Qs = sm;             // [64][132]  (d-major, q cols)
    float* Ks = sm + 64 * 132;  // [64][132]
    __shared__ int msk[128];

    int bh = blockIdx.y;
    int b = bh >> 4, h = bh & 15;
    int q0 = blockIdx.x << 7;
    int tid = threadIdx.x, tx = tid & 15, ty = tid >> 4;

    // Load Q tile (128 x 64), transposed + pre-scaled by 1/sqrt(64)
    {
        int q  = tid >> 1;
        int d0 = (tid & 1) << 5;
        const float* src = Qh + (size_t)(b * S_ + q0 + q) * DM + h * DK + d0;
        #pragma unroll
        for (int i = 0; i < 8; i++) {
            float4 v = *(const float4*)(src + (i << 2));
            int d = d0 + (i << 2);
            Qs[(d + 0) * 132 + q] = v.x * 0.125f;
            Qs[(d + 1) * 132 + q] = v.y * 0.125f;
            Qs[(d + 2) * 132 + q] = v.z * 0.125f;
            Qs[(d + 3) * 132 + q] = v.w * 0.125f;
        }
    }

    float rmax[8];
    #pragma unroll
    for (int i = 0; i < 8; i++) rmax[i] = -3.0e38f;

    for (int kt = 0; kt < 16; kt++) {
        int kb = kt << 7;
        __syncthreads();
        {
            int kq = tid >> 1;
            int d0 = (tid & 1) << 5;
            const float* src = Kh + (size_t)(b * S_ + kb + kq) * DM + h * DK + d0;
            #pragma unroll
            for (int i = 0; i < 8; i++) {
                float4 v = *(const float4*)(src + (i << 2));
                int d = d0 + (i << 2);
                Ks[(d + 0) * 132 + kq] = v.x;
                Ks[(d + 1) * 132 + kq] = v.y;
                Ks[(d + 2) * 132 + kq] = v.z;
                Ks[(d + 3) * 132 + kq] = v.w;
            }
            if (tid < 128) msk[tid] = mask[b * S_ + kb + tid];
        }
        __syncthreads();

        float acc[8][8];
        #pragma unroll
        for (int i = 0; i < 8; i++)
            #pragma unroll
            for (int j = 0; j < 8; j++) acc[i][j] = 0.0f;

        #pragma unroll 16
        for (int kk = 0; kk < 64; kk++) {
            float a[8], bb[8];
            *(float4*)(a)      = *(const float4*)&Qs[kk * 132 + (ty << 2)];
            *(float4*)(a + 4)  = *(const float4*)&Qs[kk * 132 + 64 + (ty << 2)];
            *(float4*)(bb)     = *(const float4*)&Ks[kk * 132 + (tx << 2)];
            *(float4*)(bb + 4) = *(const float4*)&Ks[kk * 132 + 64 + (tx << 2)];
            #pragma unroll
            for (int i = 0; i < 8; i++)
                #pragma unroll
                for (int j = 0; j < 8; j++) acc[i][j] += a[i] * bb[j];
        }

        #pragma unroll
        for (int i = 0; i < 8; i++) {
            int qr = (i < 4) ? ((ty << 2) + i) : (64 + (ty << 2) + i - 4);
            float* orow = attn + ((size_t)bh * S_ + q0 + qr) * S_ + kb;
            float o0[4], o1[4];
            #pragma unroll
            for (int j = 0; j < 4; j++) {
                float s = msk[(tx << 2) + j] ? acc[i][j] : NEG_INF_F;
                rmax[i] = fmaxf(rmax[i], s);
                o0[j] = s;
            }
            #pragma unroll
            for (int j = 0; j < 4; j++) {
                float s = msk[64 + (tx << 2) + j] ? acc[i][4 + j] : NEG_INF_F;
                rmax[i] = fmaxf(rmax[i], s);
                o1[j] = s;
            }
            *(float4*)(orow + (tx << 2))      = make_float4(o0[0], o0[1], o0[2], o0[3]);
            *(float4*)(orow + 64 + (tx << 2)) = make_float4(o1[0], o1[1], o1[2], o1[3]);
        }
    }

    // Reduce row max across the 16 tx lanes (width-16 shuffle groups)
    #pragma unroll
    for (int i = 0; i < 8; i++) {
        float m = rmax[i];
        m = fmaxf(m, __shfl_xor_sync(0xffffffffu, m, 1, 16));
        m = fmaxf(m, __shfl_xor_sync(0xffffffffu, m, 2, 16));
        m = fmaxf(m, __shfl_xor_sync(0xffffffffu, m, 4, 16));
        m = fmaxf(m, __shfl_xor_sync(0xffffffffu, m, 8, 16));
        if (tx == 0) {
            int qr = (i < 4) ? ((ty << 2) + i) : (64 + (ty << 2) + i - 4);
            rowmax[(size_t)bh * S_ + q0 + qr] = m;
        }
    }
}

// ---------------------------------------------------------------------------
// Row softmax over 2048-wide rows, in place. One block per row.
// ---------------------------------------------------------------------------
__global__ void __launch_bounds__(256) softmax_kernel(
    float* __restrict__ attn, const float* __restrict__ rowmax)
{
    __shared__ float sbuf[8];
    size_t row = blockIdx.x;
    float* p = attn + row * S_;
    float m = rowmax[row];
    int t = threadIdx.x;
    float4 v0 = ((const float4*)p)[t];
    float4 v1 = ((const float4*)p)[t + 256];
    float e[8];
    e[0] = __expf(v0.x - m); e[1] = __expf(v0.y - m);
    e[2] = __expf(v0.z - m); e[3] = __expf(v0.w - m);
    e[4] = __expf(v1.x - m); e[5] = __expf(v1.y - m);
    e[6] = __expf(v1.z - m); e[7] = __expf(v1.w - m);
    float s = e[0] + e[1] + e[2] + e[3] + e[4] + e[5] + e[6] + e[7];
    float l = blk_sum256(s, sbuf);
    float inv = 1.0f / l;
    ((float4*)p)[t]       = make_float4(e[0]*inv, e[1]*inv, e[2]*inv, e[3]*inv);
    ((float4*)p)[t + 256] = make_float4(e[4]*inv, e[5]*inv, e[6]*inv, e[7]*inv);
}

// ---------------------------------------------------------------------------
// PV: ctx[b,q,h,:] = attn[b,h,q,:] @ V[b,:,h,:].  Per (b,h): (2048x2048)@(2048x64).
// 128x64 block tile, BK=16, 256 threads, 8x4 micro-tile.
// ---------------------------------------------------------------------------
__global__ void __launch_bounds__(256) pv_kernel(
    const float* __restrict__ attn, const float* __restrict__ Vh,
    float* __restrict__ ctx)
{
    __shared__ float Ps[16][132];
    __shared__ float Vs[16][68];
    int bh = blockIdx.y;
    int b = bh >> 4, h = bh & 15;
    int m0 = blockIdx.x << 7;
    int tid = threadIdx.x, tx = tid & 15, ty = tid >> 4;

    float acc[8][4];
    #pragma unroll
    for (int i = 0; i < 8; i++)
        #pragma unroll
        for (int j = 0; j < 4; j++) acc[i][j] = 0.0f;

    const float* P = attn + ((size_t)bh * S_ + m0) * S_;
    const float* V = Vh + (size_t)b * S_ * DM + h * DK;
    int prow = tid >> 1;
    int pk0  = (tid & 1) << 3;
    int vk   = tid >> 4;
    int vn   = (tid & 15) << 2;

    for (int k0 = 0; k0 < S_; k0 += 16) {
        __syncthreads();
        float4 p0 = *(const float4*)(P + (size_t)prow * S_ + k0 + pk0);
        float4 p1 = *(const float4*)(P + (size_t)prow * S_ + k0 + pk0 + 4);
        Ps[pk0 + 0][prow] = p0.x; Ps[pk0 + 1][prow] = p0.y;
        Ps[pk0 + 2][prow] = p0.z; Ps[pk0 + 3][prow] = p0.w;
        Ps[pk0 + 4][prow] = p1.x; Ps[pk0 + 5][prow] = p1.y;
        Ps[pk0 + 6][prow] = p1.z; Ps[pk0 + 7][prow] = p1.w;
        *(float4*)&Vs[vk][vn] = *(const float4*)(V + (size_t)(k0 + vk) * DM + vn);
        __syncthreads();
        #pragma unroll
        for (int kk = 0; kk < 16; kk++) {
            float a[8], bb[4];
            *(float4*)(a)     = *(const float4*)&Ps[kk][ty << 2];
            *(float4*)(a + 4) = *(const float4*)&Ps[kk][64 + (ty << 2)];
            *(float4*)(bb)    = *(const float4*)&Vs[kk][tx << 2];
            #pragma unroll
            for (int i = 0; i < 8; i++)
                #pragma unroll
                for (int j = 0; j < 4; j++) acc[i][j] += a[i] * bb[j];
        }
    }

    #pragma unroll
    for (int i = 0; i < 8; i++) {
        int r = (i < 4) ? ((ty << 2) + i) : (64 + (ty << 2) + i - 4);
        float4 c = make_float4(acc[i][0], acc[i][1], acc[i][2], acc[i][3]);
        *(float4*)(ctx + (size_t)(b * S_ + m0 + r) * DM + h * DK + (tx << 2)) = c;
    }
}

// ---------------------------------------------------------------------------
extern "C" void kernel_launch(void* const* d_in, const int* in_sizes, int n_in,
                              void* d_out, int out_size)
{
    const float* q    = (const float*)d_in[0];
    const float* k    = (const float*)d_in[1];
    const float* v    = (const float*)d_in[2];
    const int*   mask = (const int*)  d_in[3];
    const float* Wq   = (const float*)d_in[4];
    const float* Wk   = (const float*)d_in[5];
    const float* Wv   = (const float*)d_in[6];
    const float* Wo   = (const float*)d_in[7];
    const float* lg   = (const float*)d_in[8];
    const float* lb   = (const float*)d_in[9];

    float* out  = (float*)d_out;
    float* attn = out + ATTN_OFF;

    float *qn, *Qh, *Kh, *Vh, *ctx, *rmx;
    cudaGetSymbolAddress((void**)&qn,  g_qn);
    cudaGetSymbolAddress((void**)&Qh,  g_Qh);
    cudaGetSymbolAddress((void**)&Kh,  g_Kh);
    cudaGetSymbolAddress((void**)&Vh,  g_Vh);
    cudaGetSymbolAddress((void**)&ctx, g_ctx);
    cudaGetSymbolAddress((void**)&rmx, g_rowmax);

    cudaFuncSetAttribute(scores_kernel,
                         cudaFuncAttributeMaxDynamicSharedMemorySize, 67584);

    // 1. LayerNorm(q)
    ln_kernel<<<BS_, 256>>>(q, lg, lb, qn);

    // 2-4. Projections
    dim3 g8(DM / 128, BS_ / 128);   // (8, 64)
    sgemm_kernel<<<g8, 256>>>(qn, Wq, nullptr, Qh, BS_, DM, DM);
    sgemm_kernel<<<g8, 256>>>(k,  Wk, nullptr, Kh, BS_, DM, DM);
    sgemm_kernel<<<g8, 256>>>(v,  Wv, nullptr, Vh, BS_, DM, DM);

    // 5. Raw masked scores + row max
    scores_kernel<<<dim3(S_ / 128, B_ * H_), 256, 67584>>>(Qh, Kh, mask, attn, rmx);

    // 6. Softmax in place
    softmax_kernel<<<B_ * H_ * S_, 256>>>(attn, rmx);

    // 7. PV
    pv_kernel<<<dim3(S_ / 128, B_ * H_), 256>>>(attn, Vh, ctx);

    // 8. Output projection + residual
    sgemm_kernel<<<g8, 256>>>(ctx, Wo, q, out, BS_, DM, DM);
}